// round 17
// baseline (speedup 1.0000x reference)
#include <cuda_runtime.h>
#include <cuda_bf16.h>

// Depthwise 3x3 conv, pad=1: x (2,16,256,64,64) fp32, W (256,256,3,3) -> diag only.
// 256-bit access variant: warp = image, 4 groups of 8 lanes, each lane owns an
// 8-float segment and 16 rows slide through a 3-row register window.
#define C_CH   256
#define H_SP   64
#define W_SP   64
#define N_IMG  (2 * 16 * C_CH)   // 8192 images
#define QH     16                // rows per 8-lane group

// 256-bit global load (non-coherent).
__device__ __forceinline__ void ldg256(const float* p, float* d)
{
    unsigned r0, r1, r2, r3, r4, r5, r6, r7;
    asm("ld.global.nc.v8.b32 {%0,%1,%2,%3,%4,%5,%6,%7}, [%8];"
        : "=r"(r0), "=r"(r1), "=r"(r2), "=r"(r3),
          "=r"(r4), "=r"(r5), "=r"(r6), "=r"(r7)
        : "l"(p));
    d[0] = __uint_as_float(r0); d[1] = __uint_as_float(r1);
    d[2] = __uint_as_float(r2); d[3] = __uint_as_float(r3);
    d[4] = __uint_as_float(r4); d[5] = __uint_as_float(r5);
    d[6] = __uint_as_float(r6); d[7] = __uint_as_float(r7);
}

__device__ __forceinline__ void zero8(float* d)
{
    #pragma unroll
    for (int i = 0; i < 8; i++) d[i] = 0.f;
}

// Horizontal halo across an 8-lane group: l = prev lane's v[7], r = next lane's v[0],
// zeroed at the group boundaries.
__device__ __forceinline__ void halo8(const float* v, int lane8, float& l, float& r)
{
    l = __shfl_up_sync(0xffffffffu, v[7], 1);
    r = __shfl_down_sync(0xffffffffu, v[0], 1);
    if (lane8 == 0) l = 0.f;
    if (lane8 == 7) r = 0.f;
}

__global__ __launch_bounds__(256)
void dwconv3x3_v8_kernel(const float* __restrict__ x,
                         const float* __restrict__ Wf,
                         float* __restrict__ y)
{
    const int tid   = threadIdx.x;
    const int warp  = tid >> 5;
    const int lane  = tid & 31;
    const int lane8 = lane & 7;
    const int grp   = lane >> 3;                 // 0..3 : 16-row quarter

    const int image = blockIdx.x * 8 + warp;     // 0..8191
    const int c     = image & (C_CH - 1);
    const int top   = grp * QH;                  // 0,16,32,48
    const int col   = lane8 << 3;                // 0,8,...,56

    // Diagonal filter W[c][c][ky][kx] — warp-uniform.
    const float* wp = Wf + (size_t)c * (C_CH + 1) * 9;
    const float w00 = __ldg(wp + 0), w01 = __ldg(wp + 1), w02 = __ldg(wp + 2);
    const float w10 = __ldg(wp + 3), w11 = __ldg(wp + 4), w12 = __ldg(wp + 5);
    const float w20 = __ldg(wp + 6), w21 = __ldg(wp + 7), w22 = __ldg(wp + 8);

    const float* xin  = x + (size_t)image * (H_SP * W_SP) + col;
    float*       yout = y + (size_t)image * (H_SP * W_SP) + col;

    // 3-row register window (8 floats each) + halos.
    float a[8], b[8], cc[8];
    float la, ra, lb, rb, lc_, rc_;

    if (top >= 1) ldg256(xin + (top - 1) * W_SP, a); else zero8(a);
    ldg256(xin +  top      * W_SP, b);
    ldg256(xin + (top + 1) * W_SP, cc);          // top+1 <= 49, always valid
    halo8(a,  lane8, la, ra);
    halo8(b,  lane8, lb, rb);
    halo8(cc, lane8, lc_, rc_);

    #pragma unroll
    for (int r = 0; r < QH; r++) {
        // Prefetch row top+r+2 (clamped + zero-select; only grp==3 can go OOB).
        const int  gpre  = top + r + 2;
        const int  gclmp = (gpre < H_SP - 1) ? gpre : (H_SP - 1);
        const bool oob   = (gpre >= H_SP);

        float p[8];
        ldg256(xin + gclmp * W_SP, p);           // unconditional issue
        if (oob) zero8(p);

        float lp, rp;
        halo8(p, lane8, lp, rp);

        // Output row top+r.
        float o[8];
        o[0] = w00*la + w01*a[0] + w02*a[1]
             + w10*lb + w11*b[0] + w12*b[1]
             + w20*lc_ + w21*cc[0] + w22*cc[1];
        #pragma unroll
        for (int i = 1; i < 7; i++) {
            o[i] = w00*a[i-1] + w01*a[i] + w02*a[i+1]
                 + w10*b[i-1] + w11*b[i] + w12*b[i+1]
                 + w20*cc[i-1] + w21*cc[i] + w22*cc[i+1];
        }
        o[7] = w00*a[6] + w01*a[7] + w02*ra
             + w10*b[6] + w11*b[7] + w12*rb
             + w20*cc[6] + w21*cc[7] + w22*rc_;

        // Two 128-bit stores (stores are fire-and-forget; width not critical).
        float4 o0 = make_float4(o[0], o[1], o[2], o[3]);
        float4 o1 = make_float4(o[4], o[5], o[6], o[7]);
        *(float4*)(yout + (top + r) * W_SP)     = o0;
        *(float4*)(yout + (top + r) * W_SP + 4) = o1;

        // Slide the window.
        #pragma unroll
        for (int i = 0; i < 8; i++) { a[i] = b[i]; b[i] = cc[i]; cc[i] = p[i]; }
        la = lb; ra = rb;
        lb = lc_; rb = rc_;
        lc_ = lp; rc_ = rp;
    }
}

extern "C" void kernel_launch(void* const* d_in, const int* in_sizes, int n_in,
                              void* d_out, int out_size)
{
    const float* x  = (const float*)d_in[0];   // (S,B,C,H,W) fp32
    const float* Wf = (const float*)d_in[1];   // (C,C,3,3)  fp32
    float* y = (float*)d_out;

    dwconv3x3_v8_kernel<<<N_IMG / 8, 256>>>(x, Wf, y);
}